// round 16
// baseline (speedup 1.0000x reference)
#include <cuda_runtime.h>
#include <math.h>

#define BB 16
#define HH 512
#define WW 512
#define WORDS_PER_ROW 16     // 512 / 32 (u32 words)
#define SROW 17              // smem row stride: 16 words + 1 zero pad
#define WROWS 40             // window rows: 8 strip rows + 2*16 halo
#define NBLK (64 * 16)       // 1024 fused_edt blocks

// Scratch (no cudaMalloc allowed)
__device__ unsigned g_bits[BB * HH * WORDS_PER_ROW];  // 512 KB bitmask of gt!=0
__device__ float g_partial[NBLK];                     // per-strip partials
__device__ unsigned g_count;                          // last-block ticket (0-init)

// ---------------------------------------------------------------------------
// Kernel 1: pack gt (int32) -> bitmask. One thread per output BYTE (8 px).
// ---------------------------------------------------------------------------
__global__ void pack_bits(const int4* __restrict__ gt4) {
    int t = blockIdx.x * blockDim.x + threadIdx.x;   // one thread per 8 pixels
    int4 a = gt4[2 * t];
    int4 c = gt4[2 * t + 1];
    unsigned byte = (a.x != 0 ? 1u : 0u)  | (a.y != 0 ? 2u : 0u)
                  | (a.z != 0 ? 4u : 0u)  | (a.w != 0 ? 8u : 0u)
                  | (c.x != 0 ? 16u : 0u) | (c.y != 0 ? 32u : 0u)
                  | (c.z != 0 ? 64u : 0u) | (c.w != 0 ? 128u : 0u);
    ((unsigned char*)g_bits)[t] = (unsigned char)byte;
}

// ---------------------------------------------------------------------------
// Exact global fallback: scan full-image bitmask with distance pruning.
// Reachable only when no fg within radius 16 — correctness insurance.
// ---------------------------------------------------------------------------
__device__ __noinline__ float global_fallback(int b, int gi, int gj, float best) {
    const unsigned* base = g_bits + ((size_t)b * HH * WORDS_PER_ROW);
    for (int dd = 0; dd < HH; ++dd) {
        float dd2 = (float)(dd * dd);
        if (dd2 >= best) break;
        for (int sgn = 0; sgn < 2; ++sgn) {
            if (sgn && dd == 0) continue;
            int r = sgn ? gi + dd : gi - dd;
            if (r < 0 || r >= HH) continue;
            const unsigned* row = base + r * WORDS_PER_ROW;
            for (int w = 0; w < WORDS_PER_ROW; ++w) {
                unsigned word = row[w];
                while (word) {
                    int bit = __ffs(word) - 1;
                    word &= word - 1;
                    float dj = (float)((w << 5) + bit - gj);
                    best = fminf(best, dd2 + dj * dj);
                }
            }
        }
    }
    return best;
}

// ---------------------------------------------------------------------------
// Cold path (P ~ 2^-25 per pixel): exact expanding-Chebyshev-ring search over
// the 40-row strip window, then exact global fallback. lr in [16,23] so
// lr +- 16 stays in [0,39].
// ---------------------------------------------------------------------------
__device__ __forceinline__ int bit_at(const unsigned* s, int row, int col) {
    if (col < 0 || col >= WW) return 0;
    return (int)((s[row * SROW + (col >> 5)] >> (col & 31)) & 1u);
}

__device__ __noinline__ float ring_search_strip(const unsigned* s,
                                                int lr, int c, int b, int gi) {
    float best = 1e30f;
    for (int r = 3; r <= 16; ++r) {
        float rr = (float)(r * r);
        if (rr >= best) break;
        for (int dj = -r; dj <= r; ++dj) {
            if (bit_at(s, lr - r, c + dj) | bit_at(s, lr + r, c + dj))
                best = fminf(best, rr + (float)(dj * dj));
        }
        for (int di = -(r - 1); di <= r - 1; ++di) {
            if (bit_at(s, lr + di, c - r) | bit_at(s, lr + di, c + r))
                best = fminf(best, rr + (float)(di * di));
        }
    }
    if (best > 289.0f)
        best = global_fallback(b, gi, c, best);
    return best;
}

// ---------------------------------------------------------------------------
// Kernel 2: fused exact EDT + sqrt + probs multiply + full reduction.
// Block = 8-row x 512-col strip; window = 40 bit-rows in smem (u32 + pad).
// Thread = 1 row x 16 cols. Aligned cumulative class masks built word-wide,
// then TELESCOPED evaluation:
//   dist = [~a0]*1 + [~a1]*(s2-1) + [~a2]*(2-s2) + [~a4]*(s5-2) + [~a5]*(s8-s5)
// Dense term = 16 predicated adds; ~a1 is 2^-5 sparse -> ffs loop; cold
// (~a8, 2^-25) gets exact ring search with (true - s8) correction.
// Grid: (64 strips, 16 batches) = 1024 blocks; block 256.
// ---------------------------------------------------------------------------
__global__ void fused_edt(const float* __restrict__ probs,
                          float* __restrict__ out) {
    __shared__ unsigned s[WROWS * SROW];   // 2720 B
    __shared__ float wsum[8];
    __shared__ int is_last;

    int st  = blockIdx.x;            // strip index, 0..63
    int b   = blockIdx.y;            // batch
    int r0  = st * 8;                // first image row of strip
    int tid = threadIdx.x;

    // Fill window rows [r0-16, r0+24); outside image = 0; pad word = 0.
    const unsigned* bits = g_bits + (size_t)b * HH * WORDS_PER_ROW;
    for (int idx = tid; idx < WROWS * SROW; idx += 256) {
        int row = idx / SROW;
        int w   = idx - row * SROW;
        int gi  = r0 - 16 + row;
        s[idx] = (w < 16 && gi >= 0 && gi < HH) ? bits[gi * WORDS_PER_ROW + w] : 0u;
    }
    __syncthreads();

    int row = tid >> 5;              // 0..7, row within strip
    int cg  = tid & 31;              // column group, 16 cols each
    int lr  = 16 + row;              // local window row
    int gi  = r0 + row;              // global image row
    int c0  = cg * 16;               // first column of this thread

    // Extract 5 row-fields: bit j of F[m] = column (c0 - 2 + j).
    unsigned F[5];
    {
        int off = c0 - 2;
        int w   = (off < 0) ? 0 : (off >> 5);
        int sh  = off & 31;
        #pragma unroll
        for (int m = 0; m < 5; ++m) {
            const unsigned* sr = s + (lr - 2 + m) * SROW;
            unsigned lo = sr[w], hi = sr[w + 1];
            F[m] = (cg == 0) ? (sr[0] << 2) : __funnelshift_r(lo, hi, sh);
        }
    }
    unsigned A  = F[2];
    unsigned C1 = F[1] | F[3];
    unsigned C2 = F[0] | F[4];

    // Aligned cumulative masks: bit p (pixel c0+p) set iff fg with d^2 <= X.
    unsigned a0 = A >> 2;
    unsigned a1 = a0 | (A >> 1)  | (A >> 3)  | (C1 >> 2);
    unsigned a2 = a1 | (C1 >> 1) | (C1 >> 3);
    unsigned a4 = a2 |  A        | (A >> 4)  | (C2 >> 2);
    unsigned a5 = a4 |  C1       | (C1 >> 4) | (C2 >> 1) | (C2 >> 3);
    unsigned a8 = a5 |  C2       | (C2 >> 4);

    unsigned n0   = ~a0 & 0xFFFFu;       // dense (~1/2)
    unsigned n1   = ~a1 & 0xFFFFu;       // sparse (~2^-5)
    unsigned cold = ~a8 & 0xFFFFu;       // essentially never (~2^-25)

    // probs layout [B, 2, H, W] channel 0; 4 x float4 = 16 contiguous floats.
    const float* prow = probs + (((size_t)b * 2) * HH + gi) * WW;
    float4 p0 = *(const float4*)&prow[c0];
    float4 p1 = *(const float4*)&prow[c0 + 4];
    float4 p2 = *(const float4*)&prow[c0 + 8];
    float4 p3 = *(const float4*)&prow[c0 + 12];
    float pv[16] = {p0.x, p0.y, p0.z, p0.w, p1.x, p1.y, p1.z, p1.w,
                    p2.x, p2.y, p2.z, p2.w, p3.x, p3.y, p3.z, p3.w};

    // Dense telescoped term: +1 * pv for every non-foreground pixel.
    float acc = 0.0f;
    #pragma unroll
    for (int p = 0; p < 16; ++p)
        if (n0 & (1u << p)) acc += pv[p];

    // Sparse corrections (expected ~0.5 iterations per thread).
    const float W1 = 0.41421356237309515f;   // sqrt(2) - 1
    const float W2 = 0.58578643762690485f;   // 2 - sqrt(2)
    const float W4 = 0.23606797749978969f;   // sqrt(5) - 2
    const float W5 = 0.59235904410332070f;   // sqrt(8) - sqrt(5)
    while (n1) {
        int p = __ffs(n1) - 1;
        n1 &= n1 - 1;
        unsigned bit = 1u << p;
        float c = W1;
        if (~a2 & bit) c += W2;
        if (~a4 & bit) c += W4;
        if (~a5 & bit) c += W5;
        acc += c * pv[p];
    }

    // Deferred exact handling of cold pixels: telescoped chain already
    // contributed sqrt(8); add the difference to the true distance.
    while (cold) {
        int p = __ffs(cold) - 1;
        cold &= cold - 1;
        float dist = sqrtf(ring_search_strip(s, lr, c0 + p, b, gi));
        acc += (dist - 2.82842712474619029f) * pv[p];
    }

    // deterministic block reduction (8 warps)
    #pragma unroll
    for (int off = 16; off > 0; off >>= 1)
        acc += __shfl_down_sync(0xffffffffu, acc, off);
    if ((tid & 31) == 0) wsum[tid >> 5] = acc;
    __syncthreads();
    if (tid < 8) {
        float v = wsum[tid];
        #pragma unroll
        for (int off = 4; off > 0; off >>= 1)
            v += __shfl_down_sync(0x000000ffu, v, off);
        if (tid == 0) {
            g_partial[blockIdx.y * 64 + blockIdx.x] = v;
            __threadfence();
            unsigned ticket = atomicAdd(&g_count, 1u);
            is_last = (ticket == NBLK - 1);
        }
    }
    __syncthreads();

    // Last block reduces all partials in a fixed order (deterministic).
    if (is_last) {
        __threadfence();
        float v = g_partial[tid] + g_partial[tid + 256]
                + g_partial[tid + 512] + g_partial[tid + 768];
        #pragma unroll
        for (int off = 16; off > 0; off >>= 1)
            v += __shfl_down_sync(0xffffffffu, v, off);
        if ((tid & 31) == 0) wsum[tid >> 5] = v;
        __syncthreads();
        if (tid < 8) {
            float w = wsum[tid];
            #pragma unroll
            for (int off = 4; off > 0; off >>= 1)
                w += __shfl_down_sync(0x000000ffu, w, off);
            if (tid == 0) {
                out[0] = w * (1.0f / (float)((size_t)BB * HH * WW));
                g_count = 0;   // self-reset for graph replay
            }
        }
    }
}

extern "C" void kernel_launch(void* const* d_in, const int* in_sizes, int n_in,
                              void* d_out, int out_size) {
    const float* probs = (const float*)d_in[0];
    const int*   gt    = (const int*)d_in[1];
    float* out = (float*)d_out;

    // one thread per 8 pixels: 4194304 / 8 / 256 = 2048 blocks
    pack_bits<<<2048, 256>>>((const int4*)gt);
    dim3 grid(64, BB);
    fused_edt<<<grid, 256>>>(probs, out);
}